// round 5
// baseline (speedup 1.0000x reference)
#include <cuda_runtime.h>
#include <math.h>
#include <stdint.h>

#define BATCH  4
#define SEQ    2048
#define DMODEL 768
#define NHEAD  12
#define HDIM   64
#define MTOT   (BATCH*SEQ)

// ---------------- scratch (static device globals; no allocs allowed) ----------------
__device__ float g_q[MTOT*DMODEL];
__device__ float g_k[MTOT*DMODEL];
__device__ float g_v[MTOT*DMODEL];
__device__ float g_att[MTOT*DMODEL];
__device__ unsigned char g_ctx[MTOT];
__device__ int g_is_byte;

// ---------------- is_context dtype detection ----------------
__global__ void detect_dtype_kernel(const unsigned char* __restrict__ p, int nbytes) {
    __shared__ int found;
    if (threadIdx.x == 0) found = 0;
    __syncthreads();
    int loc = 0;
    for (int i = threadIdx.x; i < nbytes; i += blockDim.x)
        if ((i & 3) == 1 && p[i] != 0) loc = 1;
    if (loc) atomicOr(&found, 1);
    __syncthreads();
    if (threadIdx.x == 0) g_is_byte = found;
}

__global__ void ctx_convert_kernel(const void* __restrict__ p, int n) {
    int i = blockIdx.x * blockDim.x + threadIdx.x;
    if (i >= n) return;
    int v;
    if (g_is_byte) v = ((const unsigned char*)p)[i];
    else           v = ((const int*)p)[i];
    g_ctx[i] = v ? 1 : 0;
}

// ---------------- fast exp on the FMA pipe (x <= 0; validated round 3) ----------------
__device__ __forceinline__ float fast_exp(float x) {
    float t = fmaxf(x * 1.4426950408889634f, -126.0f);
    float fi = floorf(t);
    float g  = (t - fi) * 0.6931471805599453f;
    float p;
    p = fmaf(g, 1.0f/720.0f, 1.0f/120.0f);
    p = fmaf(g, p, 1.0f/24.0f);
    p = fmaf(g, p, 1.0f/6.0f);
    p = fmaf(g, p, 0.5f);
    p = fmaf(g, p, 1.0f);
    p = fmaf(g, p, 1.0f);
    int e = (int)fi;
    float sc = __int_as_float((e + 127) << 23);
    return p * sc;
}

// ---------------- tf32 helpers ----------------
__device__ __forceinline__ uint32_t to_tf32(float x) {
    uint32_t r;
    asm("cvt.rna.tf32.f32 %0, %1;" : "=r"(r) : "f"(x));
    return r;
}

__device__ __forceinline__ void mma_tf32(float* d, const uint32_t* a, const uint32_t* b, const float* c) {
    asm volatile(
        "mma.sync.aligned.m16n8k8.row.col.f32.tf32.tf32.f32 "
        "{%0,%1,%2,%3}, {%4,%5,%6,%7}, {%8,%9}, {%10,%11,%12,%13};"
        : "=f"(d[0]), "=f"(d[1]), "=f"(d[2]), "=f"(d[3])
        : "r"(a[0]), "r"(a[1]), "r"(a[2]), "r"(a[3]),
          "r"(b[0]), "r"(b[1]),
          "f"(c[0]), "f"(c[1]), "f"(c[2]), "f"(c[3]));
}

// ---------------- tf32 tensor-core GEMM with LDG prefetch pipeline ----------------
// C[M,768] = A[M,768] @ W[768,768]^T + bias.  CTA tile 128x128, BK=32,
// 256 threads = 8 warps (4M x 2N), warp tile 32x64.  blockIdx.z selects
// which of up to 3 (W, bias, C) triples to use (QKV fused launch).
__global__ __launch_bounds__(256) void gemm_tc_kernel(
    const float* __restrict__ A,
    const float* __restrict__ W0, const float* __restrict__ b0, float* __restrict__ C0,
    const float* __restrict__ W1, const float* __restrict__ b1, float* __restrict__ C1,
    const float* __restrict__ W2, const float* __restrict__ b2, float* __restrict__ C2)
{
    __shared__ uint32_t As[32][132];   // [k][m], tf32
    __shared__ uint32_t Bs[32][136];   // [k][n], tf32  (B[k][n] = W[n][k])

    int z = blockIdx.z;
    const float* W    = (z == 0) ? W0 : (z == 1) ? W1 : W2;
    const float* bias = (z == 0) ? b0 : (z == 1) ? b1 : b2;
    float*       C    = (z == 0) ? C0 : (z == 1) ? C1 : C2;

    int t    = threadIdx.x;
    int lane = t & 31;
    int warp = t >> 5;
    int g    = lane >> 2;
    int tq   = lane & 3;
    int wm   = (warp & 3) * 32;
    int wn   = (warp >> 2) * 64;
    int m0   = blockIdx.y * 128;
    int n0   = blockIdx.x * 128;

    float acc[2][8][4];
#pragma unroll
    for (int mt = 0; mt < 2; mt++)
#pragma unroll
        for (int nt = 0; nt < 8; nt++)
#pragma unroll
            for (int c = 0; c < 4; c++) acc[mt][nt][c] = 0.f;

    int r  = t & 127;          // row within tile (both A-m and W-n)
    int kg = (t >> 7) * 16;    // k sub-block

    const float* Arow = A + (size_t)(m0 + r) * DMODEL + kg;
    const float* Wrow = W + (size_t)(n0 + r) * DMODEL + kg;

    // prefetch iter 0
    float4 pa[4], pb[4];
#pragma unroll
    for (int u = 0; u < 4; u++) {
        pa[u] = *(const float4*)&Arow[4 * u];
        pb[u] = *(const float4*)&Wrow[4 * u];
    }

    for (int k0 = 0; k0 < DMODEL; k0 += 32) {
        __syncthreads();   // previous compute done
        // stage prefetched regs -> smem (tf32)
#pragma unroll
        for (int u = 0; u < 4; u++) {
            As[kg + 4*u + 0][r] = to_tf32(pa[u].x);
            As[kg + 4*u + 1][r] = to_tf32(pa[u].y);
            As[kg + 4*u + 2][r] = to_tf32(pa[u].z);
            As[kg + 4*u + 3][r] = to_tf32(pa[u].w);
            Bs[kg + 4*u + 0][r] = to_tf32(pb[u].x);
            Bs[kg + 4*u + 1][r] = to_tf32(pb[u].y);
            Bs[kg + 4*u + 2][r] = to_tf32(pb[u].z);
            Bs[kg + 4*u + 3][r] = to_tf32(pb[u].w);
        }
        __syncthreads();   // tile ready

        // prefetch next iter (wrapped address; values unused on last iter)
        int kn = (k0 + 32 < DMODEL) ? (k0 + 32) : 0;
#pragma unroll
        for (int u = 0; u < 4; u++) {
            pa[u] = *(const float4*)&Arow[kn + 4 * u];
            pb[u] = *(const float4*)&Wrow[kn + 4 * u];
        }

        // compute (overlaps the prefetch LDGs)
#pragma unroll
        for (int kk = 0; kk < 4; kk++) {
            uint32_t af[2][4];
#pragma unroll
            for (int mt = 0; mt < 2; mt++) {
                int rb = wm + mt * 16;
                af[mt][0] = As[kk*8 + tq    ][rb + g    ];
                af[mt][1] = As[kk*8 + tq    ][rb + g + 8];
                af[mt][2] = As[kk*8 + tq + 4][rb + g    ];
                af[mt][3] = As[kk*8 + tq + 4][rb + g + 8];
            }
#pragma unroll
            for (int nt = 0; nt < 8; nt++) {
                uint32_t bf[2];
                bf[0] = Bs[kk*8 + tq    ][wn + nt*8 + g];
                bf[1] = Bs[kk*8 + tq + 4][wn + nt*8 + g];
                mma_tf32(acc[0][nt], af[0], bf, acc[0][nt]);
                mma_tf32(acc[1][nt], af[1], bf, acc[1][nt]);
            }
        }
    }

    // epilogue
#pragma unroll
    for (int mt = 0; mt < 2; mt++) {
#pragma unroll
        for (int nt = 0; nt < 8; nt++) {
            int row = m0 + wm + mt * 16 + g;
            int col = n0 + wn + nt * 8 + 2 * tq;
            float b0v = bias[col], b1v = bias[col + 1];
            float2 o0 = make_float2(acc[mt][nt][0] + b0v, acc[mt][nt][1] + b1v);
            float2 o1 = make_float2(acc[mt][nt][2] + b0v, acc[mt][nt][3] + b1v);
            *(float2*)&C[(size_t)row * DMODEL + col]       = o0;
            *(float2*)&C[(size_t)(row + 8) * DMODEL + col] = o1;
        }
    }
}

// ---------------- Flash attention on tensor cores (prefetch pipeline + fast_exp) ----------------
// grid (SEQ/128, NHEAD, BATCH), 256 threads = 8 warps, warp owns 16 query rows.
__global__ __launch_bounds__(256) void attn_tc_kernel() {
    __shared__ uint32_t Ks[32][68];        // [key][dim] tf32
    __shared__ uint32_t Vs[32][68];        // [key][dim] tf32
    __shared__ uint32_t Ps[8][16][36];     // per-warp P tile, tf32
    __shared__ float km[32];               // 0 or -1e30 per key

    int t    = threadIdx.x;
    int lane = t & 31;
    int w    = t >> 5;
    int g    = lane >> 2;
    int tq   = lane & 3;

    int b  = blockIdx.z;
    int h  = blockIdx.y;
    int qrow = blockIdx.x * 128 + w * 16;

    // Q fragments (scale folded), kept in regs for all 64 KV tiles
    uint32_t qa[8][4];
    {
        const float* qb = &g_q[(size_t)(b * SEQ + qrow) * DMODEL + h * HDIM];
#pragma unroll
        for (int ks = 0; ks < 8; ks++) {
            qa[ks][0] = to_tf32(qb[(size_t)g       * DMODEL + ks*8 + tq    ] * 0.125f);
            qa[ks][1] = to_tf32(qb[(size_t)(g + 8) * DMODEL + ks*8 + tq    ] * 0.125f);
            qa[ks][2] = to_tf32(qb[(size_t)g       * DMODEL + ks*8 + tq + 4] * 0.125f);
            qa[ks][3] = to_tf32(qb[(size_t)(g + 8) * DMODEL + ks*8 + tq + 4] * 0.125f);
        }
    }
    float rf0 = g_ctx[b * SEQ + qrow + g    ] ? 1.f : 0.f;
    float rf1 = g_ctx[b * SEQ + qrow + g + 8] ? 1.f : 0.f;

    float o[8][4];
#pragma unroll
    for (int nt = 0; nt < 8; nt++)
#pragma unroll
        for (int c = 0; c < 4; c++) o[nt][c] = 0.f;
    float m0r = -1e30f, m1r = -1e30f, l0 = 0.f, l1 = 0.f;

    // staging geometry: 2 float4 slots per thread per array
    int key0 = t >> 4,            c40 = t & 15;
    int key1 = (t + 256) >> 4,    c41 = (t + 256) & 15;
    size_t sbase = (size_t)(b * SEQ) * DMODEL + h * HDIM;

    // prefetch tile 0
    float4 pk0 = *(const float4*)&g_k[sbase + (size_t)key0 * DMODEL + c40 * 4];
    float4 pk1 = *(const float4*)&g_k[sbase + (size_t)key1 * DMODEL + c41 * 4];
    float4 pv0 = *(const float4*)&g_v[sbase + (size_t)key0 * DMODEL + c40 * 4];
    float4 pv1 = *(const float4*)&g_v[sbase + (size_t)key1 * DMODEL + c41 * 4];
    unsigned char pcm = (t < 32) ? g_ctx[b * SEQ + t] : 0;

    for (int k0 = 0; k0 < SEQ; k0 += 32) {
        __syncthreads();   // previous tile consumed
        Ks[key0][c40*4 + 0] = to_tf32(pk0.x); Ks[key0][c40*4 + 1] = to_tf32(pk0.y);
        Ks[key0][c40*4 + 2] = to_tf32(pk0.z); Ks[key0][c40*4 + 3] = to_tf32(pk0.w);
        Ks[key1][c41*4 + 0] = to_tf32(pk1.x); Ks[key1][c41*4 + 1] = to_tf32(pk1.y);
        Ks[key1][c41*4 + 2] = to_tf32(pk1.z); Ks[key1][c41*4 + 3] = to_tf32(pk1.w);
        Vs[key0][c40*4 + 0] = to_tf32(pv0.x); Vs[key0][c40*4 + 1] = to_tf32(pv0.y);
        Vs[key0][c40*4 + 2] = to_tf32(pv0.z); Vs[key0][c40*4 + 3] = to_tf32(pv0.w);
        Vs[key1][c41*4 + 0] = to_tf32(pv1.x); Vs[key1][c41*4 + 1] = to_tf32(pv1.y);
        Vs[key1][c41*4 + 2] = to_tf32(pv1.z); Vs[key1][c41*4 + 3] = to_tf32(pv1.w);
        if (t < 32) km[t] = pcm ? 0.f : -1e30f;
        __syncthreads();   // tile ready

        // prefetch next tile (wrapped; unused on last iter)
        {
            int kn = (k0 + 32) & (SEQ - 1);
            size_t nb = sbase + (size_t)kn * DMODEL;
            pk0 = *(const float4*)&g_k[nb + (size_t)key0 * DMODEL + c40 * 4];
            pk1 = *(const float4*)&g_k[nb + (size_t)key1 * DMODEL + c41 * 4];
            pv0 = *(const float4*)&g_v[nb + (size_t)key0 * DMODEL + c40 * 4];
            pv1 = *(const float4*)&g_v[nb + (size_t)key1 * DMODEL + c41 * 4];
            if (t < 32) pcm = g_ctx[b * SEQ + kn + t];
        }

        // ---- S = Q K^T (16 x 32) ----
        float sacc[4][4];
#pragma unroll
        for (int nt = 0; nt < 4; nt++)
#pragma unroll
            for (int c = 0; c < 4; c++) sacc[nt][c] = 0.f;
#pragma unroll
        for (int ks = 0; ks < 8; ks++) {
#pragma unroll
            for (int nt = 0; nt < 4; nt++) {
                uint32_t bf[2];
                bf[0] = Ks[nt*8 + g][ks*8 + tq    ];
                bf[1] = Ks[nt*8 + g][ks*8 + tq + 4];
                mma_tf32(sacc[nt], qa[ks], bf, sacc[nt]);
            }
        }

        // ---- mask (additive -1e30, branchless) ----
#pragma unroll
        for (int nt = 0; nt < 4; nt++) {
            int col = nt*8 + 2*tq;
            float k0m = km[col], k1m = km[col + 1];
            sacc[nt][0] = fmaf(rf0, k0m, sacc[nt][0]);
            sacc[nt][1] = fmaf(rf0, k1m, sacc[nt][1]);
            sacc[nt][2] = fmaf(rf1, k0m, sacc[nt][2]);
            sacc[nt][3] = fmaf(rf1, k1m, sacc[nt][3]);
        }

        // ---- online softmax (fast_exp on FMA pipe) ----
        float mx0 = -1e30f, mx1 = -1e30f;
#pragma unroll
        for (int nt = 0; nt < 4; nt++) {
            mx0 = fmaxf(mx0, fmaxf(sacc[nt][0], sacc[nt][1]));
            mx1 = fmaxf(mx1, fmaxf(sacc[nt][2], sacc[nt][3]));
        }
        mx0 = fmaxf(mx0, __shfl_xor_sync(0xffffffffu, mx0, 1));
        mx0 = fmaxf(mx0, __shfl_xor_sync(0xffffffffu, mx0, 2));
        mx1 = fmaxf(mx1, __shfl_xor_sync(0xffffffffu, mx1, 1));
        mx1 = fmaxf(mx1, __shfl_xor_sync(0xffffffffu, mx1, 2));

        float mn0 = fmaxf(m0r, mx0), mn1 = fmaxf(m1r, mx1);
        float corr0 = fast_exp(m0r - mn0), corr1 = fast_exp(m1r - mn1);
        m0r = mn0; m1r = mn1;

        float rs0 = 0.f, rs1 = 0.f;
        __syncwarp();
#pragma unroll
        for (int nt = 0; nt < 4; nt++) {
            int col = nt*8 + 2*tq;
            float p00 = fast_exp(sacc[nt][0] - mn0);
            float p01 = fast_exp(sacc[nt][1] - mn0);
            float p10 = fast_exp(sacc[nt][2] - mn1);
            float p11 = fast_exp(sacc[nt][3] - mn1);
            rs0 += p00 + p01; rs1 += p10 + p11;
            Ps[w][g    ][col    ] = to_tf32(p00);
            Ps[w][g    ][col + 1] = to_tf32(p01);
            Ps[w][g + 8][col    ] = to_tf32(p10);
            Ps[w][g + 8][col + 1] = to_tf32(p11);
        }
        rs0 += __shfl_xor_sync(0xffffffffu, rs0, 1);
        rs0 += __shfl_xor_sync(0xffffffffu, rs0, 2);
        rs1 += __shfl_xor_sync(0xffffffffu, rs1, 1);
        rs1 += __shfl_xor_sync(0xffffffffu, rs1, 2);
        l0 = l0 * corr0 + rs0;
        l1 = l1 * corr1 + rs1;

#pragma unroll
        for (int nt = 0; nt < 8; nt++) {
            o[nt][0] *= corr0; o[nt][1] *= corr0;
            o[nt][2] *= corr1; o[nt][3] *= corr1;
        }
        __syncwarp();

        // ---- O += P V  (16 x 64, k=32) ----
#pragma unroll
        for (int ks = 0; ks < 4; ks++) {
            uint32_t ap[4];
            ap[0] = Ps[w][g    ][ks*8 + tq    ];
            ap[1] = Ps[w][g + 8][ks*8 + tq    ];
            ap[2] = Ps[w][g    ][ks*8 + tq + 4];
            ap[3] = Ps[w][g + 8][ks*8 + tq + 4];
#pragma unroll
            for (int nt = 0; nt < 8; nt++) {
                uint32_t bf[2];
                bf[0] = Vs[ks*8 + tq    ][nt*8 + g];
                bf[1] = Vs[ks*8 + tq + 4][nt*8 + g];
                mma_tf32(o[nt], ap, bf, o[nt]);
            }
        }
    }

    // ---- normalize + write ----
    float inv0 = 1.f / l0, inv1 = 1.f / l1;
    float* ob = &g_att[(size_t)(b * SEQ + qrow) * DMODEL + h * HDIM];
#pragma unroll
    for (int nt = 0; nt < 8; nt++) {
        int col = nt*8 + 2*tq;
        *(float2*)&ob[(size_t)g       * DMODEL + col] = make_float2(o[nt][0] * inv0, o[nt][1] * inv0);
        *(float2*)&ob[(size_t)(g + 8) * DMODEL + col] = make_float2(o[nt][2] * inv1, o[nt][3] * inv1);
    }
}

// ---------------- launch ----------------
extern "C" void kernel_launch(void* const* d_in, const int* in_sizes, int n_in,
                              void* d_out, int out_size) {
    const float* x   = (const float*)d_in[0];
    const void*  ctx = d_in[1];
    const float* Wq  = (const float*)d_in[2];
    const float* bq  = (const float*)d_in[3];
    const float* Wk  = (const float*)d_in[4];
    const float* bk  = (const float*)d_in[5];
    const float* Wv  = (const float*)d_in[6];
    const float* bv  = (const float*)d_in[7];
    const float* Wo  = (const float*)d_in[8];
    const float* bo  = (const float*)d_in[9];
    float* out = (float*)d_out;

    float *qb, *kb, *vb, *ab;
    cudaGetSymbolAddress((void**)&qb, g_q);
    cudaGetSymbolAddress((void**)&kb, g_k);
    cudaGetSymbolAddress((void**)&vb, g_v);
    cudaGetSymbolAddress((void**)&ab, g_att);

    detect_dtype_kernel<<<1, 1024>>>((const unsigned char*)ctx, MTOT);
    ctx_convert_kernel<<<(MTOT + 255) / 256, 256>>>(ctx, MTOT);

    // fused QKV projections: blockIdx.z selects (W, bias, C)
    dim3 gqkv(DMODEL / 128, MTOT / 128, 3);  // (6, 64, 3)
    gemm_tc_kernel<<<gqkv, 256>>>(x, Wq, bq, qb, Wk, bk, kb, Wv, bv, vb);

    attn_tc_kernel<<<dim3(SEQ / 128, NHEAD, BATCH), 256>>>();

    // O projection
    dim3 go(DMODEL / 128, MTOT / 128, 1);
    gemm_tc_kernel<<<go, 256>>>(ab, Wo, bo, out, Wo, bo, out, Wo, bo, out);
}

// round 6
// speedup vs baseline: 1.0911x; 1.0911x over previous
#include <cuda_runtime.h>
#include <math.h>
#include <stdint.h>

#define BATCH  4
#define SEQ    2048
#define DMODEL 768
#define NHEAD  12
#define HDIM   64
#define MTOT   (BATCH*SEQ)

// ---------------- scratch (static device globals; no allocs allowed) ----------------
__device__ float g_q[MTOT*DMODEL];
__device__ float g_k[MTOT*DMODEL];
__device__ float g_v[MTOT*DMODEL];
__device__ float g_att[MTOT*DMODEL];
__device__ unsigned char g_ctx[MTOT];
__device__ int g_is_byte;

// ---------------- is_context dtype detection ----------------
__global__ void detect_dtype_kernel(const unsigned char* __restrict__ p, int nbytes) {
    __shared__ int found;
    if (threadIdx.x == 0) found = 0;
    __syncthreads();
    int loc = 0;
    for (int i = threadIdx.x; i < nbytes; i += blockDim.x)
        if ((i & 3) == 1 && p[i] != 0) loc = 1;
    if (loc) atomicOr(&found, 1);
    __syncthreads();
    if (threadIdx.x == 0) g_is_byte = found;
}

__global__ void ctx_convert_kernel(const void* __restrict__ p, int n) {
    int i = blockIdx.x * blockDim.x + threadIdx.x;
    if (i >= n) return;
    int v;
    if (g_is_byte) v = ((const unsigned char*)p)[i];
    else           v = ((const int*)p)[i];
    g_ctx[i] = v ? 1 : 0;
}

// ---------------- fast exp on the FMA pipe (x <= 0) ----------------
__device__ __forceinline__ float fast_exp(float x) {
    float t = fmaxf(x * 1.4426950408889634f, -126.0f);
    float fi = floorf(t);
    float g  = (t - fi) * 0.6931471805599453f;
    float p;
    p = fmaf(g, 1.0f/720.0f, 1.0f/120.0f);
    p = fmaf(g, p, 1.0f/24.0f);
    p = fmaf(g, p, 1.0f/6.0f);
    p = fmaf(g, p, 0.5f);
    p = fmaf(g, p, 1.0f);
    p = fmaf(g, p, 1.0f);
    int e = (int)fi;
    float sc = __int_as_float((e + 127) << 23);
    return p * sc;
}

// ---------------- tf32 / cp.async helpers ----------------
__device__ __forceinline__ uint32_t to_tf32(float x) {
    uint32_t r;
    asm("cvt.rna.tf32.f32 %0, %1;" : "=r"(r) : "f"(x));
    return r;
}

__device__ __forceinline__ void mma_tf32(float* d, const uint32_t* a, const uint32_t* b, const float* c) {
    asm volatile(
        "mma.sync.aligned.m16n8k8.row.col.f32.tf32.tf32.f32 "
        "{%0,%1,%2,%3}, {%4,%5,%6,%7}, {%8,%9}, {%10,%11,%12,%13};"
        : "=f"(d[0]), "=f"(d[1]), "=f"(d[2]), "=f"(d[3])
        : "r"(a[0]), "r"(a[1]), "r"(a[2]), "r"(a[3]),
          "r"(b[0]), "r"(b[1]),
          "f"(c[0]), "f"(c[1]), "f"(c[2]), "f"(c[3]));
}

__device__ __forceinline__ void cp_async16(uint32_t saddr, const void* gptr) {
    asm volatile("cp.async.cg.shared.global [%0], [%1], 16;" :: "r"(saddr), "l"(gptr));
}
__device__ __forceinline__ void cp_async4(uint32_t saddr, const void* gptr) {
    asm volatile("cp.async.ca.shared.global [%0], [%1], 4;" :: "r"(saddr), "l"(gptr));
}
__device__ __forceinline__ void cp_commit() {
    asm volatile("cp.async.commit_group;" ::: "memory");
}
__device__ __forceinline__ void cp_wait1() {
    asm volatile("cp.async.wait_group 1;" ::: "memory");
}
__device__ __forceinline__ void cp_wait0() {
    asm volatile("cp.async.wait_group 0;" ::: "memory");
}

// ---------------- tf32 tensor-core GEMM with LDG prefetch pipeline (round-5, kept) ----------------
__global__ __launch_bounds__(256) void gemm_tc_kernel(
    const float* __restrict__ A,
    const float* __restrict__ W0, const float* __restrict__ b0, float* __restrict__ C0,
    const float* __restrict__ W1, const float* __restrict__ b1, float* __restrict__ C1,
    const float* __restrict__ W2, const float* __restrict__ b2, float* __restrict__ C2)
{
    __shared__ uint32_t As[32][132];
    __shared__ uint32_t Bs[32][136];

    int z = blockIdx.z;
    const float* W    = (z == 0) ? W0 : (z == 1) ? W1 : W2;
    const float* bias = (z == 0) ? b0 : (z == 1) ? b1 : b2;
    float*       C    = (z == 0) ? C0 : (z == 1) ? C1 : C2;

    int t    = threadIdx.x;
    int lane = t & 31;
    int warp = t >> 5;
    int g    = lane >> 2;
    int tq   = lane & 3;
    int wm   = (warp & 3) * 32;
    int wn   = (warp >> 2) * 64;
    int m0   = blockIdx.y * 128;
    int n0   = blockIdx.x * 128;

    float acc[2][8][4];
#pragma unroll
    for (int mt = 0; mt < 2; mt++)
#pragma unroll
        for (int nt = 0; nt < 8; nt++)
#pragma unroll
            for (int c = 0; c < 4; c++) acc[mt][nt][c] = 0.f;

    int r  = t & 127;
    int kg = (t >> 7) * 16;

    const float* Arow = A + (size_t)(m0 + r) * DMODEL + kg;
    const float* Wrow = W + (size_t)(n0 + r) * DMODEL + kg;

    float4 pa[4], pb[4];
#pragma unroll
    for (int u = 0; u < 4; u++) {
        pa[u] = *(const float4*)&Arow[4 * u];
        pb[u] = *(const float4*)&Wrow[4 * u];
    }

    for (int k0 = 0; k0 < DMODEL; k0 += 32) {
        __syncthreads();
#pragma unroll
        for (int u = 0; u < 4; u++) {
            As[kg + 4*u + 0][r] = to_tf32(pa[u].x);
            As[kg + 4*u + 1][r] = to_tf32(pa[u].y);
            As[kg + 4*u + 2][r] = to_tf32(pa[u].z);
            As[kg + 4*u + 3][r] = to_tf32(pa[u].w);
            Bs[kg + 4*u + 0][r] = to_tf32(pb[u].x);
            Bs[kg + 4*u + 1][r] = to_tf32(pb[u].y);
            Bs[kg + 4*u + 2][r] = to_tf32(pb[u].z);
            Bs[kg + 4*u + 3][r] = to_tf32(pb[u].w);
        }
        __syncthreads();

        int kn = (k0 + 32 < DMODEL) ? (k0 + 32) : 0;
#pragma unroll
        for (int u = 0; u < 4; u++) {
            pa[u] = *(const float4*)&Arow[kn + 4 * u];
            pb[u] = *(const float4*)&Wrow[kn + 4 * u];
        }

#pragma unroll
        for (int kk = 0; kk < 4; kk++) {
            uint32_t af[2][4];
#pragma unroll
            for (int mt = 0; mt < 2; mt++) {
                int rb = wm + mt * 16;
                af[mt][0] = As[kk*8 + tq    ][rb + g    ];
                af[mt][1] = As[kk*8 + tq    ][rb + g + 8];
                af[mt][2] = As[kk*8 + tq + 4][rb + g    ];
                af[mt][3] = As[kk*8 + tq + 4][rb + g + 8];
            }
#pragma unroll
            for (int nt = 0; nt < 8; nt++) {
                uint32_t bf[2];
                bf[0] = Bs[kk*8 + tq    ][wn + nt*8 + g];
                bf[1] = Bs[kk*8 + tq + 4][wn + nt*8 + g];
                mma_tf32(acc[0][nt], af[0], bf, acc[0][nt]);
                mma_tf32(acc[1][nt], af[1], bf, acc[1][nt]);
            }
        }
    }

#pragma unroll
    for (int mt = 0; mt < 2; mt++) {
#pragma unroll
        for (int nt = 0; nt < 8; nt++) {
            int row = m0 + wm + mt * 16 + g;
            int col = n0 + wn + nt * 8 + 2 * tq;
            float b0v = bias[col], b1v = bias[col + 1];
            float2 o0 = make_float2(acc[mt][nt][0] + b0v, acc[mt][nt][1] + b1v);
            float2 o1 = make_float2(acc[mt][nt][2] + b0v, acc[mt][nt][3] + b1v);
            *(float2*)&C[(size_t)row * DMODEL + col]       = o0;
            *(float2*)&C[(size_t)(row + 8) * DMODEL + col] = o1;
        }
    }
}

// ---------------- Flash attention: cp.async double-buffered, 2 CTAs/SM ----------------
// grid (SEQ/128, NHEAD, BATCH), 256 threads = 8 warps, warp owns 16 query rows.
// K/V staged as RAW fp32 via cp.async (no staging registers); cvt.rna.tf32 at
// fragment-load time (identical numerics to converting at stage time).
__global__ __launch_bounds__(256, 2) void attn_tc_kernel() {
    __shared__ __align__(16) float Ksf[2][32][68];
    __shared__ __align__(16) float Vsf[2][32][68];
    __shared__ uint32_t Ps[8][16][36];
    __shared__ unsigned char cs[2][32];

    int t    = threadIdx.x;
    int lane = t & 31;
    int w    = t >> 5;
    int g    = lane >> 2;
    int tq   = lane & 3;

    int b  = blockIdx.z;
    int h  = blockIdx.y;
    int qrow = blockIdx.x * 128 + w * 16;

    // Q fragments (scale folded), tf32, in regs for all 64 KV tiles
    uint32_t qa[8][4];
    {
        const float* qb = &g_q[(size_t)(b * SEQ + qrow) * DMODEL + h * HDIM];
#pragma unroll
        for (int ks = 0; ks < 8; ks++) {
            qa[ks][0] = to_tf32(qb[(size_t)g       * DMODEL + ks*8 + tq    ] * 0.125f);
            qa[ks][1] = to_tf32(qb[(size_t)(g + 8) * DMODEL + ks*8 + tq    ] * 0.125f);
            qa[ks][2] = to_tf32(qb[(size_t)g       * DMODEL + ks*8 + tq + 4] * 0.125f);
            qa[ks][3] = to_tf32(qb[(size_t)(g + 8) * DMODEL + ks*8 + tq + 4] * 0.125f);
        }
    }
    float rf0 = g_ctx[b * SEQ + qrow + g    ] ? 1.f : 0.f;
    float rf1 = g_ctx[b * SEQ + qrow + g + 8] ? 1.f : 0.f;

    float o[8][4];
#pragma unroll
    for (int nt = 0; nt < 8; nt++)
#pragma unroll
        for (int c = 0; c < 4; c++) o[nt][c] = 0.f;
    float m0r = -1e30f, m1r = -1e30f, l0 = 0.f, l1 = 0.f;

    // staging geometry: 2 float4 slots per thread per array
    int key0 = t >> 4,         c40 = t & 15;
    int key1 = (t + 256) >> 4, c41 = (t + 256) & 15;
    size_t sbase = (size_t)(b * SEQ) * DMODEL + h * HDIM;

    uint32_t ks_s = (uint32_t)__cvta_generic_to_shared(&Ksf[0][0][0]);
    uint32_t vs_s = (uint32_t)__cvta_generic_to_shared(&Vsf[0][0][0]);
    uint32_t cs_s = (uint32_t)__cvta_generic_to_shared(&cs[0][0]);

    // stage one KV tile (32 keys x 64 dims) into buffer `buf` with cp.async
    auto stage = [&](int buf, int kt) {
        size_t nb = sbase + (size_t)kt * DMODEL;
        uint32_t bo = (uint32_t)buf * (32 * 68 * 4);
        cp_async16(ks_s + bo + (key0 * 68 + c40 * 4) * 4, &g_k[nb + (size_t)key0 * DMODEL + c40 * 4]);
        cp_async16(ks_s + bo + (key1 * 68 + c41 * 4) * 4, &g_k[nb + (size_t)key1 * DMODEL + c41 * 4]);
        cp_async16(vs_s + bo + (key0 * 68 + c40 * 4) * 4, &g_v[nb + (size_t)key0 * DMODEL + c40 * 4]);
        cp_async16(vs_s + bo + (key1 * 68 + c41 * 4) * 4, &g_v[nb + (size_t)key1 * DMODEL + c41 * 4]);
        if (t < 8) cp_async4(cs_s + buf * 32 + t * 4, &g_ctx[b * SEQ + kt + t * 4]);
        cp_commit();
    };

    stage(0, 0);

    const int NT = SEQ / 32;   // 64 tiles
    for (int tile = 0; tile < NT; tile++) {
        int buf = tile & 1;
        if (tile + 1 < NT) {
            stage(buf ^ 1, (tile + 1) * 32);
            cp_wait1();           // current tile's group complete
        } else {
            cp_wait0();
        }
        __syncthreads();          // tile visible to all warps

        const float (*Kt)[68] = Ksf[buf];
        const float (*Vt)[68] = Vsf[buf];

        // ---- S = Q K^T (16 x 32) ----
        float sacc[4][4];
#pragma unroll
        for (int nt = 0; nt < 4; nt++)
#pragma unroll
            for (int c = 0; c < 4; c++) sacc[nt][c] = 0.f;
#pragma unroll
        for (int ks = 0; ks < 8; ks++) {
#pragma unroll
            for (int nt = 0; nt < 4; nt++) {
                uint32_t bf[2];
                bf[0] = to_tf32(Kt[nt*8 + g][ks*8 + tq    ]);
                bf[1] = to_tf32(Kt[nt*8 + g][ks*8 + tq + 4]);
                mma_tf32(sacc[nt], qa[ks], bf, sacc[nt]);
            }
        }

        // ---- mask (additive -1e30, branchless; == reference) ----
#pragma unroll
        for (int nt = 0; nt < 4; nt++) {
            int col = nt*8 + 2*tq;
            float k0m = cs[buf][col    ] ? 0.f : -1e30f;
            float k1m = cs[buf][col + 1] ? 0.f : -1e30f;
            sacc[nt][0] = fmaf(rf0, k0m, sacc[nt][0]);
            sacc[nt][1] = fmaf(rf0, k1m, sacc[nt][1]);
            sacc[nt][2] = fmaf(rf1, k0m, sacc[nt][2]);
            sacc[nt][3] = fmaf(rf1, k1m, sacc[nt][3]);
        }

        // ---- online softmax ----
        float mx0 = -1e30f, mx1 = -1e30f;
#pragma unroll
        for (int nt = 0; nt < 4; nt++) {
            mx0 = fmaxf(mx0, fmaxf(sacc[nt][0], sacc[nt][1]));
            mx1 = fmaxf(mx1, fmaxf(sacc[nt][2], sacc[nt][3]));
        }
        mx0 = fmaxf(mx0, __shfl_xor_sync(0xffffffffu, mx0, 1));
        mx0 = fmaxf(mx0, __shfl_xor_sync(0xffffffffu, mx0, 2));
        mx1 = fmaxf(mx1, __shfl_xor_sync(0xffffffffu, mx1, 1));
        mx1 = fmaxf(mx1, __shfl_xor_sync(0xffffffffu, mx1, 2));

        float mn0 = fmaxf(m0r, mx0), mn1 = fmaxf(m1r, mx1);
        float corr0 = fast_exp(m0r - mn0), corr1 = fast_exp(m1r - mn1);
        m0r = mn0; m1r = mn1;

        float rs0 = 0.f, rs1 = 0.f;
        __syncwarp();
#pragma unroll
        for (int nt = 0; nt < 4; nt++) {
            int col = nt*8 + 2*tq;
            float p00 = fast_exp(sacc[nt][0] - mn0);
            float p01 = fast_exp(sacc[nt][1] - mn0);
            float p10 = fast_exp(sacc[nt][2] - mn1);
            float p11 = fast_exp(sacc[nt][3] - mn1);
            rs0 += p00 + p01; rs1 += p10 + p11;
            Ps[w][g    ][col    ] = to_tf32(p00);
            Ps[w][g    ][col + 1] = to_tf32(p01);
            Ps[w][g + 8][col    ] = to_tf32(p10);
            Ps[w][g + 8][col + 1] = to_tf32(p11);
        }
        rs0 += __shfl_xor_sync(0xffffffffu, rs0, 1);
        rs0 += __shfl_xor_sync(0xffffffffu, rs0, 2);
        rs1 += __shfl_xor_sync(0xffffffffu, rs1, 1);
        rs1 += __shfl_xor_sync(0xffffffffu, rs1, 2);
        l0 = l0 * corr0 + rs0;
        l1 = l1 * corr1 + rs1;

#pragma unroll
        for (int nt = 0; nt < 8; nt++) {
            o[nt][0] *= corr0; o[nt][1] *= corr0;
            o[nt][2] *= corr1; o[nt][3] *= corr1;
        }
        __syncwarp();

        // ---- O += P V  (16 x 64, k=32) ----
#pragma unroll
        for (int ks = 0; ks < 4; ks++) {
            uint32_t ap[4];
            ap[0] = Ps[w][g    ][ks*8 + tq    ];
            ap[1] = Ps[w][g + 8][ks*8 + tq    ];
            ap[2] = Ps[w][g    ][ks*8 + tq + 4];
            ap[3] = Ps[w][g + 8][ks*8 + tq + 4];
#pragma unroll
            for (int nt = 0; nt < 8; nt++) {
                uint32_t bf[2];
                bf[0] = to_tf32(Vt[ks*8 + tq    ][nt*8 + g]);
                bf[1] = to_tf32(Vt[ks*8 + tq + 4][nt*8 + g]);
                mma_tf32(o[nt], ap, bf, o[nt]);
            }
        }
        __syncthreads();   // everyone done with buffer `buf` before restaging it
    }

    // ---- normalize + write ----
    float inv0 = 1.f / l0, inv1 = 1.f / l1;
    float* ob = &g_att[(size_t)(b * SEQ + qrow) * DMODEL + h * HDIM];
#pragma unroll
    for (int nt = 0; nt < 8; nt++) {
        int col = nt*8 + 2*tq;
        *(float2*)&ob[(size_t)g       * DMODEL + col] = make_float2(o[nt][0] * inv0, o[nt][1] * inv0);
        *(float2*)&ob[(size_t)(g + 8) * DMODEL + col] = make_float2(o[nt][2] * inv1, o[nt][3] * inv1);
    }
}

// ---------------- launch ----------------
extern "C" void kernel_launch(void* const* d_in, const int* in_sizes, int n_in,
                              void* d_out, int out_size) {
    const float* x   = (const float*)d_in[0];
    const void*  ctx = d_in[1];
    const float* Wq  = (const float*)d_in[2];
    const float* bq  = (const float*)d_in[3];
    const float* Wk  = (const float*)d_in[4];
    const float* bk  = (const float*)d_in[5];
    const float* Wv  = (const float*)d_in[6];
    const float* bv  = (const float*)d_in[7];
    const float* Wo  = (const float*)d_in[8];
    const float* bo  = (const float*)d_in[9];
    float* out = (float*)d_out;

    float *qb, *kb, *vb, *ab;
    cudaGetSymbolAddress((void**)&qb, g_q);
    cudaGetSymbolAddress((void**)&kb, g_k);
    cudaGetSymbolAddress((void**)&vb, g_v);
    cudaGetSymbolAddress((void**)&ab, g_att);

    detect_dtype_kernel<<<1, 1024>>>((const unsigned char*)ctx, MTOT);
    ctx_convert_kernel<<<(MTOT + 255) / 256, 256>>>(ctx, MTOT);

    dim3 gqkv(DMODEL / 128, MTOT / 128, 3);
    gemm_tc_kernel<<<gqkv, 256>>>(x, Wq, bq, qb, Wk, bk, kb, Wv, bv, vb);

    attn_tc_kernel<<<dim3(SEQ / 128, NHEAD, BATCH), 256>>>();

    dim3 go(DMODEL / 128, MTOT / 128, 1);
    gemm_tc_kernel<<<go, 256>>>(ab, Wo, bo, out, Wo, bo, out, Wo, bo, out);
}

// round 7
// speedup vs baseline: 1.4163x; 1.2980x over previous
#include <cuda_runtime.h>
#include <math.h>
#include <stdint.h>

#define BATCH  4
#define SEQ    2048
#define DMODEL 768
#define NHEAD  12
#define HDIM   64
#define MTOT   (BATCH*SEQ)

// ---------------- scratch (static device globals; no allocs allowed) ----------------
__device__ float g_q[MTOT*DMODEL];
__device__ float g_k[MTOT*DMODEL];
__device__ float g_v[MTOT*DMODEL];
__device__ float g_att[MTOT*DMODEL];
__device__ float g_xt[MTOT*DMODEL];        // x, tf32-rounded
__device__ float g_wq[DMODEL*DMODEL];      // weights, tf32-rounded
__device__ float g_wk[DMODEL*DMODEL];
__device__ float g_wv[DMODEL*DMODEL];
__device__ float g_wo[DMODEL*DMODEL];
__device__ unsigned char g_ctx[MTOT];
__device__ int g_is_byte;

// ---------------- is_context dtype detection ----------------
__global__ void detect_dtype_kernel(const unsigned char* __restrict__ p, int nbytes) {
    __shared__ int found;
    if (threadIdx.x == 0) found = 0;
    __syncthreads();
    int loc = 0;
    for (int i = threadIdx.x; i < nbytes; i += blockDim.x)
        if ((i & 3) == 1 && p[i] != 0) loc = 1;
    if (loc) atomicOr(&found, 1);
    __syncthreads();
    if (threadIdx.x == 0) g_is_byte = found;
}

__global__ void ctx_convert_kernel(const void* __restrict__ p, int n) {
    int i = blockIdx.x * blockDim.x + threadIdx.x;
    if (i >= n) return;
    int v;
    if (g_is_byte) v = ((const unsigned char*)p)[i];
    else           v = ((const int*)p)[i];
    g_ctx[i] = v ? 1 : 0;
}

// ---------------- fast exp on the FMA pipe (x <= 0) ----------------
__device__ __forceinline__ float fast_exp(float x) {
    float t = fmaxf(x * 1.4426950408889634f, -126.0f);
    float fi = floorf(t);
    float g  = (t - fi) * 0.6931471805599453f;
    float p;
    p = fmaf(g, 1.0f/720.0f, 1.0f/120.0f);
    p = fmaf(g, p, 1.0f/24.0f);
    p = fmaf(g, p, 1.0f/6.0f);
    p = fmaf(g, p, 0.5f);
    p = fmaf(g, p, 1.0f);
    p = fmaf(g, p, 1.0f);
    int e = (int)fi;
    float sc = __int_as_float((e + 127) << 23);
    return p * sc;
}

// ---------------- tf32 / cp.async helpers ----------------
__device__ __forceinline__ uint32_t to_tf32(float x) {
    uint32_t r;
    asm("cvt.rna.tf32.f32 %0, %1;" : "=r"(r) : "f"(x));
    return r;
}

__device__ __forceinline__ void mma_tf32(float* d, const uint32_t* a, const uint32_t* b, const float* c) {
    asm volatile(
        "mma.sync.aligned.m16n8k8.row.col.f32.tf32.tf32.f32 "
        "{%0,%1,%2,%3}, {%4,%5,%6,%7}, {%8,%9}, {%10,%11,%12,%13};"
        : "=f"(d[0]), "=f"(d[1]), "=f"(d[2]), "=f"(d[3])
        : "r"(a[0]), "r"(a[1]), "r"(a[2]), "r"(a[3]),
          "r"(b[0]), "r"(b[1]),
          "f"(c[0]), "f"(c[1]), "f"(c[2]), "f"(c[3]));
}

__device__ __forceinline__ void cp_async16(uint32_t saddr, const void* gptr) {
    asm volatile("cp.async.cg.shared.global [%0], [%1], 16;" :: "r"(saddr), "l"(gptr));
}
__device__ __forceinline__ void cp_async4(uint32_t saddr, const void* gptr) {
    asm volatile("cp.async.ca.shared.global [%0], [%1], 4;" :: "r"(saddr), "l"(gptr));
}
__device__ __forceinline__ void cp_commit() {
    asm volatile("cp.async.commit_group;" ::: "memory");
}
__device__ __forceinline__ void cp_wait1() {
    asm volatile("cp.async.wait_group 1;" ::: "memory");
}
__device__ __forceinline__ void cp_wait0() {
    asm volatile("cp.async.wait_group 0;" ::: "memory");
}

// ---------------- tf32 pre-conversion (once per launch; cvt commutes downstream) ----------------
__global__ void tf32_convert_kernel(const float* __restrict__ src, float* __restrict__ dst, int n) {
    int i = blockIdx.x * blockDim.x + threadIdx.x;
    int stride = gridDim.x * blockDim.x;
    for (; i < n; i += stride)
        dst[i] = __uint_as_float(to_tf32(src[i]));
}

// ---------------- tf32 tensor-core GEMM, cp.async double-buffered ----------------
// C[M,768] = A[M,768] @ W[768,768]^T + bias.  A and W are PRE-tf32-rounded.
// CTA tile 128x128, BK=32, 256 threads = 8 warps (4M x 2N), warp tile 32x64.
// Smem layout [row][k] with row stride 36 words: fragment pattern (4g+tq)%32
// covers all banks -> conflict-free. blockIdx.z selects (W,bias,C); cvt_out
// rounds outputs to tf32 (for Q/K/V consumed by the attention mma).
#define GROW 36
#define GBUF (128*GROW)
__global__ __launch_bounds__(256, 2) void gemm_tc_kernel(
    const float* __restrict__ A,
    const float* __restrict__ W0, const float* __restrict__ b0, float* __restrict__ C0,
    const float* __restrict__ W1, const float* __restrict__ b1, float* __restrict__ C1,
    const float* __restrict__ W2, const float* __restrict__ b2, float* __restrict__ C2,
    int cvt_out)
{
    extern __shared__ float sm[];
    float* As = sm;               // [2][128][GROW]
    float* Bs = sm + 2 * GBUF;    // [2][128][GROW]

    int z = blockIdx.z;
    const float* W    = (z == 0) ? W0 : (z == 1) ? W1 : W2;
    const float* bias = (z == 0) ? b0 : (z == 1) ? b1 : b2;
    float*       C    = (z == 0) ? C0 : (z == 1) ? C1 : C2;

    int t    = threadIdx.x;
    int lane = t & 31;
    int warp = t >> 5;
    int g    = lane >> 2;
    int tq   = lane & 3;
    int wm   = (warp & 3) * 32;
    int wn   = (warp >> 2) * 64;
    int m0   = blockIdx.y * 128;
    int n0   = blockIdx.x * 128;

    float acc[2][8][4];
#pragma unroll
    for (int mt = 0; mt < 2; mt++)
#pragma unroll
        for (int nt = 0; nt < 8; nt++)
#pragma unroll
            for (int c = 0; c < 4; c++) acc[mt][nt][c] = 0.f;

    uint32_t as_s = (uint32_t)__cvta_generic_to_shared(As);
    uint32_t bs_s = (uint32_t)__cvta_generic_to_shared(Bs);

    // stage one BK=32 slab of A and W into buffer `buf`
    auto stage = [&](int buf, int k0) {
        uint32_t bo = (uint32_t)buf * GBUF * 4;
#pragma unroll
        for (int u = 0; u < 4; u++) {
            int c = t + 256 * u;            // 1024 16B-chunks per array
            int row = c >> 3, c16 = c & 7;
            uint32_t soff = bo + (uint32_t)(row * GROW + c16 * 4) * 4;
            cp_async16(as_s + soff, &A[(size_t)(m0 + row) * DMODEL + k0 + c16 * 4]);
            cp_async16(bs_s + soff, &W[(size_t)(n0 + row) * DMODEL + k0 + c16 * 4]);
        }
        cp_commit();
    };

    stage(0, 0);

    const int NI = DMODEL / 32;   // 24
    for (int iter = 0; iter < NI; iter++) {
        int buf = iter & 1;
        if (iter + 1 < NI) {
            stage(buf ^ 1, (iter + 1) * 32);
            cp_wait1();
        } else {
            cp_wait0();
        }
        __syncthreads();

        const float* A2 = As + buf * GBUF;
        const float* B2 = Bs + buf * GBUF;

#pragma unroll
        for (int kk = 0; kk < 4; kk++) {
            int kb = kk * 8;
            uint32_t af[2][4];
#pragma unroll
            for (int mt = 0; mt < 2; mt++) {
                int rb = wm + mt * 16;
                af[mt][0] = __float_as_uint(A2[(rb + g    ) * GROW + kb + tq    ]);
                af[mt][1] = __float_as_uint(A2[(rb + g + 8) * GROW + kb + tq    ]);
                af[mt][2] = __float_as_uint(A2[(rb + g    ) * GROW + kb + tq + 4]);
                af[mt][3] = __float_as_uint(A2[(rb + g + 8) * GROW + kb + tq + 4]);
            }
#pragma unroll
            for (int nt = 0; nt < 8; nt++) {
                uint32_t bf[2];
                bf[0] = __float_as_uint(B2[(wn + nt*8 + g) * GROW + kb + tq    ]);
                bf[1] = __float_as_uint(B2[(wn + nt*8 + g) * GROW + kb + tq + 4]);
                mma_tf32(acc[0][nt], af[0], bf, acc[0][nt]);
                mma_tf32(acc[1][nt], af[1], bf, acc[1][nt]);
            }
        }
        __syncthreads();   // all warps done with buf before it is restaged
    }

    // epilogue: bias add (+ optional tf32 rounding of outputs)
#pragma unroll
    for (int mt = 0; mt < 2; mt++) {
#pragma unroll
        for (int nt = 0; nt < 8; nt++) {
            int row = m0 + wm + mt * 16 + g;
            int col = n0 + wn + nt * 8 + 2 * tq;
            float b0v = bias[col], b1v = bias[col + 1];
            float v00 = acc[mt][nt][0] + b0v, v01 = acc[mt][nt][1] + b1v;
            float v10 = acc[mt][nt][2] + b0v, v11 = acc[mt][nt][3] + b1v;
            if (cvt_out) {
                v00 = __uint_as_float(to_tf32(v00)); v01 = __uint_as_float(to_tf32(v01));
                v10 = __uint_as_float(to_tf32(v10)); v11 = __uint_as_float(to_tf32(v11));
            }
            *(float2*)&C[(size_t)row * DMODEL + col]       = make_float2(v00, v01);
            *(float2*)&C[(size_t)(row + 8) * DMODEL + col] = make_float2(v10, v11);
        }
    }
}

// ---------------- Flash attention: cp.async double-buffered, 2 CTAs/SM ----------------
// Q/K/V are PRE-tf32-rounded by the QKV GEMM -> fragment loads are raw LDS,
// zero cvt in the mainloop. Output written tf32-rounded (consumed by O GEMM).
__global__ __launch_bounds__(256, 2) void attn_tc_kernel() {
    __shared__ __align__(16) float Ksf[2][32][68];
    __shared__ __align__(16) float Vsf[2][32][68];
    __shared__ uint32_t Ps[8][16][36];
    __shared__ unsigned char cs[2][32];

    int t    = threadIdx.x;
    int lane = t & 31;
    int w    = t >> 5;
    int g    = lane >> 2;
    int tq   = lane & 3;

    int b  = blockIdx.z;
    int h  = blockIdx.y;
    int qrow = blockIdx.x * 128 + w * 16;

    // Q fragments: already tf32-rounded; *0.125f (2^-3) is exact on tf32
    uint32_t qa[8][4];
    {
        const float* qb = &g_q[(size_t)(b * SEQ + qrow) * DMODEL + h * HDIM];
#pragma unroll
        for (int ks = 0; ks < 8; ks++) {
            qa[ks][0] = __float_as_uint(qb[(size_t)g       * DMODEL + ks*8 + tq    ] * 0.125f);
            qa[ks][1] = __float_as_uint(qb[(size_t)(g + 8) * DMODEL + ks*8 + tq    ] * 0.125f);
            qa[ks][2] = __float_as_uint(qb[(size_t)g       * DMODEL + ks*8 + tq + 4] * 0.125f);
            qa[ks][3] = __float_as_uint(qb[(size_t)(g + 8) * DMODEL + ks*8 + tq + 4] * 0.125f);
        }
    }
    float rf0 = g_ctx[b * SEQ + qrow + g    ] ? 1.f : 0.f;
    float rf1 = g_ctx[b * SEQ + qrow + g + 8] ? 1.f : 0.f;

    float o[8][4];
#pragma unroll
    for (int nt = 0; nt < 8; nt++)
#pragma unroll
        for (int c = 0; c < 4; c++) o[nt][c] = 0.f;
    float m0r = -1e30f, m1r = -1e30f, l0 = 0.f, l1 = 0.f;

    int key0 = t >> 4,         c40 = t & 15;
    int key1 = (t + 256) >> 4, c41 = (t + 256) & 15;
    size_t sbase = (size_t)(b * SEQ) * DMODEL + h * HDIM;

    uint32_t ks_s = (uint32_t)__cvta_generic_to_shared(&Ksf[0][0][0]);
    uint32_t vs_s = (uint32_t)__cvta_generic_to_shared(&Vsf[0][0][0]);
    uint32_t cs_s = (uint32_t)__cvta_generic_to_shared(&cs[0][0]);

    auto stage = [&](int buf, int kt) {
        size_t nb = sbase + (size_t)kt * DMODEL;
        uint32_t bo = (uint32_t)buf * (32 * 68 * 4);
        cp_async16(ks_s + bo + (key0 * 68 + c40 * 4) * 4, &g_k[nb + (size_t)key0 * DMODEL + c40 * 4]);
        cp_async16(ks_s + bo + (key1 * 68 + c41 * 4) * 4, &g_k[nb + (size_t)key1 * DMODEL + c41 * 4]);
        cp_async16(vs_s + bo + (key0 * 68 + c40 * 4) * 4, &g_v[nb + (size_t)key0 * DMODEL + c40 * 4]);
        cp_async16(vs_s + bo + (key1 * 68 + c41 * 4) * 4, &g_v[nb + (size_t)key1 * DMODEL + c41 * 4]);
        if (t < 8) cp_async4(cs_s + buf * 32 + t * 4, &g_ctx[b * SEQ + kt + t * 4]);
        cp_commit();
    };

    stage(0, 0);

    const int NT = SEQ / 32;   // 64 tiles
    for (int tile = 0; tile < NT; tile++) {
        int buf = tile & 1;
        if (tile + 1 < NT) {
            stage(buf ^ 1, (tile + 1) * 32);
            cp_wait1();
        } else {
            cp_wait0();
        }
        __syncthreads();

        const float (*Kt)[68] = Ksf[buf];
        const float (*Vt)[68] = Vsf[buf];

        // ---- S = Q K^T (16 x 32) ----
        float sacc[4][4];
#pragma unroll
        for (int nt = 0; nt < 4; nt++)
#pragma unroll
            for (int c = 0; c < 4; c++) sacc[nt][c] = 0.f;
#pragma unroll
        for (int ks = 0; ks < 8; ks++) {
#pragma unroll
            for (int nt = 0; nt < 4; nt++) {
                uint32_t bf[2];
                bf[0] = __float_as_uint(Kt[nt*8 + g][ks*8 + tq    ]);
                bf[1] = __float_as_uint(Kt[nt*8 + g][ks*8 + tq + 4]);
                mma_tf32(sacc[nt], qa[ks], bf, sacc[nt]);
            }
        }

        // ---- mask (additive -1e30, branchless; == reference) ----
#pragma unroll
        for (int nt = 0; nt < 4; nt++) {
            int col = nt*8 + 2*tq;
            float k0m = cs[buf][col    ] ? 0.f : -1e30f;
            float k1m = cs[buf][col + 1] ? 0.f : -1e30f;
            sacc[nt][0] = fmaf(rf0, k0m, sacc[nt][0]);
            sacc[nt][1] = fmaf(rf0, k1m, sacc[nt][1]);
            sacc[nt][2] = fmaf(rf1, k0m, sacc[nt][2]);
            sacc[nt][3] = fmaf(rf1, k1m, sacc[nt][3]);
        }

        // ---- online softmax ----
        float mx0 = -1e30f, mx1 = -1e30f;
#pragma unroll
        for (int nt = 0; nt < 4; nt++) {
            mx0 = fmaxf(mx0, fmaxf(sacc[nt][0], sacc[nt][1]));
            mx1 = fmaxf(mx1, fmaxf(sacc[nt][2], sacc[nt][3]));
        }
        mx0 = fmaxf(mx0, __shfl_xor_sync(0xffffffffu, mx0, 1));
        mx0 = fmaxf(mx0, __shfl_xor_sync(0xffffffffu, mx0, 2));
        mx1 = fmaxf(mx1, __shfl_xor_sync(0xffffffffu, mx1, 1));
        mx1 = fmaxf(mx1, __shfl_xor_sync(0xffffffffu, mx1, 2));

        float mn0 = fmaxf(m0r, mx0), mn1 = fmaxf(m1r, mx1);
        float corr0 = fast_exp(m0r - mn0), corr1 = fast_exp(m1r - mn1);
        m0r = mn0; m1r = mn1;

        float rs0 = 0.f, rs1 = 0.f;
        __syncwarp();
#pragma unroll
        for (int nt = 0; nt < 4; nt++) {
            int col = nt*8 + 2*tq;
            float p00 = fast_exp(sacc[nt][0] - mn0);
            float p01 = fast_exp(sacc[nt][1] - mn0);
            float p10 = fast_exp(sacc[nt][2] - mn1);
            float p11 = fast_exp(sacc[nt][3] - mn1);
            rs0 += p00 + p01; rs1 += p10 + p11;
            Ps[w][g    ][col    ] = to_tf32(p00);
            Ps[w][g    ][col + 1] = to_tf32(p01);
            Ps[w][g + 8][col    ] = to_tf32(p10);
            Ps[w][g + 8][col + 1] = to_tf32(p11);
        }
        rs0 += __shfl_xor_sync(0xffffffffu, rs0, 1);
        rs0 += __shfl_xor_sync(0xffffffffu, rs0, 2);
        rs1 += __shfl_xor_sync(0xffffffffu, rs1, 1);
        rs1 += __shfl_xor_sync(0xffffffffu, rs1, 2);
        l0 = l0 * corr0 + rs0;
        l1 = l1 * corr1 + rs1;

#pragma unroll
        for (int nt = 0; nt < 8; nt++) {
            o[nt][0] *= corr0; o[nt][1] *= corr0;
            o[nt][2] *= corr1; o[nt][3] *= corr1;
        }
        __syncwarp();

        // ---- O += P V  (16 x 64, k=32) ----
#pragma unroll
        for (int ks = 0; ks < 4; ks++) {
            uint32_t ap[4];
            ap[0] = Ps[w][g    ][ks*8 + tq    ];
            ap[1] = Ps[w][g + 8][ks*8 + tq    ];
            ap[2] = Ps[w][g    ][ks*8 + tq + 4];
            ap[3] = Ps[w][g + 8][ks*8 + tq + 4];
#pragma unroll
            for (int nt = 0; nt < 8; nt++) {
                uint32_t bf[2];
                bf[0] = __float_as_uint(Vt[ks*8 + tq    ][nt*8 + g]);
                bf[1] = __float_as_uint(Vt[ks*8 + tq + 4][nt*8 + g]);
                mma_tf32(o[nt], ap, bf, o[nt]);
            }
        }
        __syncthreads();
    }

    // ---- normalize + write (tf32-rounded: consumed by the O GEMM's raw path) ----
    float inv0 = 1.f / l0, inv1 = 1.f / l1;
    float* ob = &g_att[(size_t)(b * SEQ + qrow) * DMODEL + h * HDIM];
#pragma unroll
    for (int nt = 0; nt < 8; nt++) {
        int col = nt*8 + 2*tq;
        float2 o0 = make_float2(__uint_as_float(to_tf32(o[nt][0] * inv0)),
                                __uint_as_float(to_tf32(o[nt][1] * inv0)));
        float2 o1 = make_float2(__uint_as_float(to_tf32(o[nt][2] * inv1)),
                                __uint_as_float(to_tf32(o[nt][3] * inv1)));
        *(float2*)&ob[(size_t)g       * DMODEL + col] = o0;
        *(float2*)&ob[(size_t)(g + 8) * DMODEL + col] = o1;
    }
}

// ---------------- launch ----------------
extern "C" void kernel_launch(void* const* d_in, const int* in_sizes, int n_in,
                              void* d_out, int out_size) {
    const float* x   = (const float*)d_in[0];
    const void*  ctx = d_in[1];
    const float* Wq  = (const float*)d_in[2];
    const float* bq  = (const float*)d_in[3];
    const float* Wk  = (const float*)d_in[4];
    const float* bk  = (const float*)d_in[5];
    const float* Wv  = (const float*)d_in[6];
    const float* bv  = (const float*)d_in[7];
    const float* Wo  = (const float*)d_in[8];
    const float* bo  = (const float*)d_in[9];
    float* out = (float*)d_out;

    float *qb, *kb, *vb, *ab, *xt, *wq, *wk, *wv, *wo;
    cudaGetSymbolAddress((void**)&qb, g_q);
    cudaGetSymbolAddress((void**)&kb, g_k);
    cudaGetSymbolAddress((void**)&vb, g_v);
    cudaGetSymbolAddress((void**)&ab, g_att);
    cudaGetSymbolAddress((void**)&xt, g_xt);
    cudaGetSymbolAddress((void**)&wq, g_wq);
    cudaGetSymbolAddress((void**)&wk, g_wk);
    cudaGetSymbolAddress((void**)&wv, g_wv);
    cudaGetSymbolAddress((void**)&wo, g_wo);

    static bool attr_set = false;
    if (!attr_set) {
        cudaFuncSetAttribute(gemm_tc_kernel, cudaFuncAttributeMaxDynamicSharedMemorySize,
                             4 * GBUF * (int)sizeof(float));
        attr_set = true;
    }

    detect_dtype_kernel<<<1, 1024>>>((const unsigned char*)ctx, MTOT);
    ctx_convert_kernel<<<(MTOT + 255) / 256, 256>>>(ctx, MTOT);

    // pre-convert x and weights to tf32 (cvt commutes with staging/scaling)
    tf32_convert_kernel<<<592, 256>>>(x,  xt, MTOT * DMODEL);
    tf32_convert_kernel<<<592, 256>>>(Wq, wq, DMODEL * DMODEL);
    tf32_convert_kernel<<<592, 256>>>(Wk, wk, DMODEL * DMODEL);
    tf32_convert_kernel<<<592, 256>>>(Wv, wv, DMODEL * DMODEL);
    tf32_convert_kernel<<<592, 256>>>(Wo, wo, DMODEL * DMODEL);

    int smem = 4 * GBUF * (int)sizeof(float);   // 73728 B

    dim3 gqkv(DMODEL / 128, MTOT / 128, 3);
    gemm_tc_kernel<<<gqkv, 256, smem>>>(xt, wq, bq, qb, wk, bk, kb, wv, bv, vb, 1);

    attn_tc_kernel<<<dim3(SEQ / 128, NHEAD, BATCH), 256>>>();

    dim3 go(DMODEL / 128, MTOT / 128, 1);
    gemm_tc_kernel<<<go, 256, smem>>>(ab, wo, bo, out, wo, bo, out, wo, bo, out, 0);
}

// round 8
// speedup vs baseline: 1.5174x; 1.0714x over previous
#include <cuda_runtime.h>
#include <math.h>
#include <stdint.h>

#define BATCH  4
#define SEQ    2048
#define DMODEL 768
#define NHEAD  12
#define HDIM   64
#define MTOT   (BATCH*SEQ)

// ---------------- scratch (static device globals; no allocs allowed) ----------------
__device__ float g_q[MTOT*DMODEL];
__device__ float g_k[MTOT*DMODEL];
__device__ float g_v[MTOT*DMODEL];
__device__ float g_att[MTOT*DMODEL];
__device__ float g_xt[MTOT*DMODEL];        // x, tf32-rounded
__device__ float g_wq[DMODEL*DMODEL];      // weights, tf32-rounded
__device__ float g_wk[DMODEL*DMODEL];
__device__ float g_wv[DMODEL*DMODEL];
__device__ float g_wo[DMODEL*DMODEL];
__device__ unsigned char g_ctx[MTOT];
__device__ int g_is_byte;

// ---------------- is_context dtype detection ----------------
__global__ void detect_dtype_kernel(const unsigned char* __restrict__ p, int nbytes) {
    __shared__ int found;
    if (threadIdx.x == 0) found = 0;
    __syncthreads();
    int loc = 0;
    for (int i = threadIdx.x; i < nbytes; i += blockDim.x)
        if ((i & 3) == 1 && p[i] != 0) loc = 1;
    if (loc) atomicOr(&found, 1);
    __syncthreads();
    if (threadIdx.x == 0) g_is_byte = found;
}

__global__ void ctx_convert_kernel(const void* __restrict__ p, int n) {
    int i = blockIdx.x * blockDim.x + threadIdx.x;
    if (i >= n) return;
    int v;
    if (g_is_byte) v = ((const unsigned char*)p)[i];
    else           v = ((const int*)p)[i];
    g_ctx[i] = v ? 1 : 0;
}

// ---------------- tf32 / cp.async helpers ----------------
__device__ __forceinline__ uint32_t to_tf32(float x) {
    uint32_t r;
    asm("cvt.rna.tf32.f32 %0, %1;" : "=r"(r) : "f"(x));
    return r;
}

__device__ __forceinline__ void mma_tf32(float* d, const uint32_t* a, const uint32_t* b, const float* c) {
    asm volatile(
        "mma.sync.aligned.m16n8k8.row.col.f32.tf32.tf32.f32 "
        "{%0,%1,%2,%3}, {%4,%5,%6,%7}, {%8,%9}, {%10,%11,%12,%13};"
        : "=f"(d[0]), "=f"(d[1]), "=f"(d[2]), "=f"(d[3])
        : "r"(a[0]), "r"(a[1]), "r"(a[2]), "r"(a[3]),
          "r"(b[0]), "r"(b[1]),
          "f"(c[0]), "f"(c[1]), "f"(c[2]), "f"(c[3]));
}

__device__ __forceinline__ void cp_async16(uint32_t saddr, const void* gptr) {
    asm volatile("cp.async.cg.shared.global [%0], [%1], 16;" :: "r"(saddr), "l"(gptr));
}
__device__ __forceinline__ void cp_async4(uint32_t saddr, const void* gptr) {
    asm volatile("cp.async.ca.shared.global [%0], [%1], 4;" :: "r"(saddr), "l"(gptr));
}
__device__ __forceinline__ void cp_commit() {
    asm volatile("cp.async.commit_group;" ::: "memory");
}
__device__ __forceinline__ void cp_wait1() {
    asm volatile("cp.async.wait_group 1;" ::: "memory");
}
__device__ __forceinline__ void cp_wait0() {
    asm volatile("cp.async.wait_group 0;" ::: "memory");
}

// ---------------- tf32 pre-conversion (once per launch; cvt commutes downstream) ----------------
__global__ void tf32_convert_kernel(const float* __restrict__ src, float* __restrict__ dst, int n) {
    int i = blockIdx.x * blockDim.x + threadIdx.x;
    int stride = gridDim.x * blockDim.x;
    for (; i < n; i += stride)
        dst[i] = __uint_as_float(to_tf32(src[i]));
}

// ---------------- tf32 tensor-core GEMM, cp.async double-buffered (round-7, kept) ----------------
#define GROW 36
#define GBUF (128*GROW)
__global__ __launch_bounds__(256, 2) void gemm_tc_kernel(
    const float* __restrict__ A,
    const float* __restrict__ W0, const float* __restrict__ b0, float* __restrict__ C0,
    const float* __restrict__ W1, const float* __restrict__ b1, float* __restrict__ C1,
    const float* __restrict__ W2, const float* __restrict__ b2, float* __restrict__ C2,
    int cvt_out)
{
    extern __shared__ float sm[];
    float* As = sm;               // [2][128][GROW]
    float* Bs = sm + 2 * GBUF;    // [2][128][GROW]

    int z = blockIdx.z;
    const float* W    = (z == 0) ? W0 : (z == 1) ? W1 : W2;
    const float* bias = (z == 0) ? b0 : (z == 1) ? b1 : b2;
    float*       C    = (z == 0) ? C0 : (z == 1) ? C1 : C2;

    int t    = threadIdx.x;
    int lane = t & 31;
    int warp = t >> 5;
    int g    = lane >> 2;
    int tq   = lane & 3;
    int wm   = (warp & 3) * 32;
    int wn   = (warp >> 2) * 64;
    int m0   = blockIdx.y * 128;
    int n0   = blockIdx.x * 128;

    float acc[2][8][4];
#pragma unroll
    for (int mt = 0; mt < 2; mt++)
#pragma unroll
        for (int nt = 0; nt < 8; nt++)
#pragma unroll
            for (int c = 0; c < 4; c++) acc[mt][nt][c] = 0.f;

    uint32_t as_s = (uint32_t)__cvta_generic_to_shared(As);
    uint32_t bs_s = (uint32_t)__cvta_generic_to_shared(Bs);

    auto stage = [&](int buf, int k0) {
        uint32_t bo = (uint32_t)buf * GBUF * 4;
#pragma unroll
        for (int u = 0; u < 4; u++) {
            int c = t + 256 * u;
            int row = c >> 3, c16 = c & 7;
            uint32_t soff = bo + (uint32_t)(row * GROW + c16 * 4) * 4;
            cp_async16(as_s + soff, &A[(size_t)(m0 + row) * DMODEL + k0 + c16 * 4]);
            cp_async16(bs_s + soff, &W[(size_t)(n0 + row) * DMODEL + k0 + c16 * 4]);
        }
        cp_commit();
    };

    stage(0, 0);

    const int NI = DMODEL / 32;   // 24
    for (int iter = 0; iter < NI; iter++) {
        int buf = iter & 1;
        if (iter + 1 < NI) {
            stage(buf ^ 1, (iter + 1) * 32);
            cp_wait1();
        } else {
            cp_wait0();
        }
        __syncthreads();

        const float* A2 = As + buf * GBUF;
        const float* B2 = Bs + buf * GBUF;

#pragma unroll
        for (int kk = 0; kk < 4; kk++) {
            int kb = kk * 8;
            uint32_t af[2][4];
#pragma unroll
            for (int mt = 0; mt < 2; mt++) {
                int rb = wm + mt * 16;
                af[mt][0] = __float_as_uint(A2[(rb + g    ) * GROW + kb + tq    ]);
                af[mt][1] = __float_as_uint(A2[(rb + g + 8) * GROW + kb + tq    ]);
                af[mt][2] = __float_as_uint(A2[(rb + g    ) * GROW + kb + tq + 4]);
                af[mt][3] = __float_as_uint(A2[(rb + g + 8) * GROW + kb + tq + 4]);
            }
#pragma unroll
            for (int nt = 0; nt < 8; nt++) {
                uint32_t bf[2];
                bf[0] = __float_as_uint(B2[(wn + nt*8 + g) * GROW + kb + tq    ]);
                bf[1] = __float_as_uint(B2[(wn + nt*8 + g) * GROW + kb + tq + 4]);
                mma_tf32(acc[0][nt], af[0], bf, acc[0][nt]);
                mma_tf32(acc[1][nt], af[1], bf, acc[1][nt]);
            }
        }
        __syncthreads();
    }

#pragma unroll
    for (int mt = 0; mt < 2; mt++) {
#pragma unroll
        for (int nt = 0; nt < 8; nt++) {
            int row = m0 + wm + mt * 16 + g;
            int col = n0 + wn + nt * 8 + 2 * tq;
            float b0v = bias[col], b1v = bias[col + 1];
            float v00 = acc[mt][nt][0] + b0v, v01 = acc[mt][nt][1] + b1v;
            float v10 = acc[mt][nt][2] + b0v, v11 = acc[mt][nt][3] + b1v;
            if (cvt_out) {
                v00 = __uint_as_float(to_tf32(v00)); v01 = __uint_as_float(to_tf32(v01));
                v10 = __uint_as_float(to_tf32(v10)); v11 = __uint_as_float(to_tf32(v11));
            }
            *(float2*)&C[(size_t)row * DMODEL + col]       = make_float2(v00, v01);
            *(float2*)&C[(size_t)(row + 8) * DMODEL + col] = make_float2(v10, v11);
        }
    }
}

// ---------------- Flash attention: cp.async double-buffered, 2 CTAs/SM ----------------
// Exps on the MUFU pipe (__expf): with 16 warps/SM the XU pipe is idle and far
// cheaper per exp (2 issue slots) than the 14-FMA polynomial on the contended
// FMA pipe. __expf(-huge)=0 exactly -> mask semantics unchanged.
__global__ __launch_bounds__(256, 2) void attn_tc_kernel() {
    __shared__ __align__(16) float Ksf[2][32][68];
    __shared__ __align__(16) float Vsf[2][32][68];
    __shared__ uint32_t Ps[8][16][36];
    __shared__ unsigned char cs[2][32];

    int t    = threadIdx.x;
    int lane = t & 31;
    int w    = t >> 5;
    int g    = lane >> 2;
    int tq   = lane & 3;

    int b  = blockIdx.z;
    int h  = blockIdx.y;
    int qrow = blockIdx.x * 128 + w * 16;

    // Q fragments: already tf32-rounded; *0.125f (2^-3) is exact on tf32
    uint32_t qa[8][4];
    {
        const float* qb = &g_q[(size_t)(b * SEQ + qrow) * DMODEL + h * HDIM];
#pragma unroll
        for (int ks = 0; ks < 8; ks++) {
            qa[ks][0] = __float_as_uint(qb[(size_t)g       * DMODEL + ks*8 + tq    ] * 0.125f);
            qa[ks][1] = __float_as_uint(qb[(size_t)(g + 8) * DMODEL + ks*8 + tq    ] * 0.125f);
            qa[ks][2] = __float_as_uint(qb[(size_t)g       * DMODEL + ks*8 + tq + 4] * 0.125f);
            qa[ks][3] = __float_as_uint(qb[(size_t)(g + 8) * DMODEL + ks*8 + tq + 4] * 0.125f);
        }
    }
    float rf0 = g_ctx[b * SEQ + qrow + g    ] ? 1.f : 0.f;
    float rf1 = g_ctx[b * SEQ + qrow + g + 8] ? 1.f : 0.f;

    float o[8][4];
#pragma unroll
    for (int nt = 0; nt < 8; nt++)
#pragma unroll
        for (int c = 0; c < 4; c++) o[nt][c] = 0.f;
    float m0r = -1e30f, m1r = -1e30f, l0 = 0.f, l1 = 0.f;

    int key0 = t >> 4,         c40 = t & 15;
    int key1 = (t + 256) >> 4, c41 = (t + 256) & 15;
    size_t sbase = (size_t)(b * SEQ) * DMODEL + h * HDIM;

    uint32_t ks_s = (uint32_t)__cvta_generic_to_shared(&Ksf[0][0][0]);
    uint32_t vs_s = (uint32_t)__cvta_generic_to_shared(&Vsf[0][0][0]);
    uint32_t cs_s = (uint32_t)__cvta_generic_to_shared(&cs[0][0]);

    auto stage = [&](int buf, int kt) {
        size_t nb = sbase + (size_t)kt * DMODEL;
        uint32_t bo = (uint32_t)buf * (32 * 68 * 4);
        cp_async16(ks_s + bo + (key0 * 68 + c40 * 4) * 4, &g_k[nb + (size_t)key0 * DMODEL + c40 * 4]);
        cp_async16(ks_s + bo + (key1 * 68 + c41 * 4) * 4, &g_k[nb + (size_t)key1 * DMODEL + c41 * 4]);
        cp_async16(vs_s + bo + (key0 * 68 + c40 * 4) * 4, &g_v[nb + (size_t)key0 * DMODEL + c40 * 4]);
        cp_async16(vs_s + bo + (key1 * 68 + c41 * 4) * 4, &g_v[nb + (size_t)key1 * DMODEL + c41 * 4]);
        if (t < 8) cp_async4(cs_s + buf * 32 + t * 4, &g_ctx[b * SEQ + kt + t * 4]);
        cp_commit();
    };

    stage(0, 0);

    const int NT = SEQ / 32;   // 64 tiles
    for (int tile = 0; tile < NT; tile++) {
        int buf = tile & 1;
        if (tile + 1 < NT) {
            stage(buf ^ 1, (tile + 1) * 32);
            cp_wait1();
        } else {
            cp_wait0();
        }
        __syncthreads();

        const float (*Kt)[68] = Ksf[buf];
        const float (*Vt)[68] = Vsf[buf];

        // ---- S = Q K^T (16 x 32) ----
        float sacc[4][4];
#pragma unroll
        for (int nt = 0; nt < 4; nt++)
#pragma unroll
            for (int c = 0; c < 4; c++) sacc[nt][c] = 0.f;
#pragma unroll
        for (int ks = 0; ks < 8; ks++) {
#pragma unroll
            for (int nt = 0; nt < 4; nt++) {
                uint32_t bf[2];
                bf[0] = __float_as_uint(Kt[nt*8 + g][ks*8 + tq    ]);
                bf[1] = __float_as_uint(Kt[nt*8 + g][ks*8 + tq + 4]);
                mma_tf32(sacc[nt], qa[ks], bf, sacc[nt]);
            }
        }

        // ---- mask (additive -1e30, branchless; == reference) ----
#pragma unroll
        for (int nt = 0; nt < 4; nt++) {
            int col = nt*8 + 2*tq;
            float k0m = cs[buf][col    ] ? 0.f : -1e30f;
            float k1m = cs[buf][col + 1] ? 0.f : -1e30f;
            sacc[nt][0] = fmaf(rf0, k0m, sacc[nt][0]);
            sacc[nt][1] = fmaf(rf0, k1m, sacc[nt][1]);
            sacc[nt][2] = fmaf(rf1, k0m, sacc[nt][2]);
            sacc[nt][3] = fmaf(rf1, k1m, sacc[nt][3]);
        }

        // ---- online softmax (MUFU exps) ----
        float mx0 = -1e30f, mx1 = -1e30f;
#pragma unroll
        for (int nt = 0; nt < 4; nt++) {
            mx0 = fmaxf(mx0, fmaxf(sacc[nt][0], sacc[nt][1]));
            mx1 = fmaxf(mx1, fmaxf(sacc[nt][2], sacc[nt][3]));
        }
        mx0 = fmaxf(mx0, __shfl_xor_sync(0xffffffffu, mx0, 1));
        mx0 = fmaxf(mx0, __shfl_xor_sync(0xffffffffu, mx0, 2));
        mx1 = fmaxf(mx1, __shfl_xor_sync(0xffffffffu, mx1, 1));
        mx1 = fmaxf(mx1, __shfl_xor_sync(0xffffffffu, mx1, 2));

        float mn0 = fmaxf(m0r, mx0), mn1 = fmaxf(m1r, mx1);
        float corr0 = __expf(m0r - mn0), corr1 = __expf(m1r - mn1);
        m0r = mn0; m1r = mn1;

        float rs0 = 0.f, rs1 = 0.f;
        __syncwarp();
#pragma unroll
        for (int nt = 0; nt < 4; nt++) {
            int col = nt*8 + 2*tq;
            float p00 = __expf(sacc[nt][0] - mn0);
            float p01 = __expf(sacc[nt][1] - mn0);
            float p10 = __expf(sacc[nt][2] - mn1);
            float p11 = __expf(sacc[nt][3] - mn1);
            rs0 += p00 + p01; rs1 += p10 + p11;
            Ps[w][g    ][col    ] = to_tf32(p00);
            Ps[w][g    ][col + 1] = to_tf32(p01);
            Ps[w][g + 8][col    ] = to_tf32(p10);
            Ps[w][g + 8][col + 1] = to_tf32(p11);
        }
        rs0 += __shfl_xor_sync(0xffffffffu, rs0, 1);
        rs0 += __shfl_xor_sync(0xffffffffu, rs0, 2);
        rs1 += __shfl_xor_sync(0xffffffffu, rs1, 1);
        rs1 += __shfl_xor_sync(0xffffffffu, rs1, 2);
        l0 = l0 * corr0 + rs0;
        l1 = l1 * corr1 + rs1;

#pragma unroll
        for (int nt = 0; nt < 8; nt++) {
            o[nt][0] *= corr0; o[nt][1] *= corr0;
            o[nt][2] *= corr1; o[nt][3] *= corr1;
        }
        __syncwarp();

        // ---- O += P V  (16 x 64, k=32) ----
#pragma unroll
        for (int ks = 0; ks < 4; ks++) {
            uint32_t ap[4];
            ap[0] = Ps[w][g    ][ks*8 + tq    ];
            ap[1] = Ps[w][g + 8][ks*8 + tq    ];
            ap[2] = Ps[w][g    ][ks*8 + tq + 4];
            ap[3] = Ps[w][g + 8][ks*8 + tq + 4];
#pragma unroll
            for (int nt = 0; nt < 8; nt++) {
                uint32_t bf[2];
                bf[0] = __float_as_uint(Vt[ks*8 + tq    ][nt*8 + g]);
                bf[1] = __float_as_uint(Vt[ks*8 + tq + 4][nt*8 + g]);
                mma_tf32(o[nt], ap, bf, o[nt]);
            }
        }
        __syncthreads();
    }

    // ---- normalize + write (tf32-rounded: consumed by the O GEMM's raw path) ----
    float inv0 = 1.f / l0, inv1 = 1.f / l1;
    float* ob = &g_att[(size_t)(b * SEQ + qrow) * DMODEL + h * HDIM];
#pragma unroll
    for (int nt = 0; nt < 8; nt++) {
        int col = nt*8 + 2*tq;
        float2 o0 = make_float2(__uint_as_float(to_tf32(o[nt][0] * inv0)),
                                __uint_as_float(to_tf32(o[nt][1] * inv0)));
        float2 o1 = make_float2(__uint_as_float(to_tf32(o[nt][2] * inv1)),
                                __uint_as_float(to_tf32(o[nt][3] * inv1)));
        *(float2*)&ob[(size_t)g       * DMODEL + col] = o0;
        *(float2*)&ob[(size_t)(g + 8) * DMODEL + col] = o1;
    }
}

// ---------------- launch ----------------
extern "C" void kernel_launch(void* const* d_in, const int* in_sizes, int n_in,
                              void* d_out, int out_size) {
    const float* x   = (const float*)d_in[0];
    const void*  ctx = d_in[1];
    const float* Wq  = (const float*)d_in[2];
    const float* bq  = (const float*)d_in[3];
    const float* Wk  = (const float*)d_in[4];
    const float* bk  = (const float*)d_in[5];
    const float* Wv  = (const float*)d_in[6];
    const float* bv  = (const float*)d_in[7];
    const float* Wo  = (const float*)d_in[8];
    const float* bo  = (const float*)d_in[9];
    float* out = (float*)d_out;

    float *qb, *kb, *vb, *ab, *xt, *wq, *wk, *wv, *wo;
    cudaGetSymbolAddress((void**)&qb, g_q);
    cudaGetSymbolAddress((void**)&kb, g_k);
    cudaGetSymbolAddress((void**)&vb, g_v);
    cudaGetSymbolAddress((void**)&ab, g_att);
    cudaGetSymbolAddress((void**)&xt, g_xt);
    cudaGetSymbolAddress((void**)&wq, g_wq);
    cudaGetSymbolAddress((void**)&wk, g_wk);
    cudaGetSymbolAddress((void**)&wv, g_wv);
    cudaGetSymbolAddress((void**)&wo, g_wo);

    static bool attr_set = false;
    if (!attr_set) {
        cudaFuncSetAttribute(gemm_tc_kernel, cudaFuncAttributeMaxDynamicSharedMemorySize,
                             4 * GBUF * (int)sizeof(float));
        attr_set = true;
    }

    detect_dtype_kernel<<<1, 1024>>>((const unsigned char*)ctx, MTOT);
    ctx_convert_kernel<<<(MTOT + 255) / 256, 256>>>(ctx, MTOT);

    tf32_convert_kernel<<<592, 256>>>(x,  xt, MTOT * DMODEL);
    tf32_convert_kernel<<<592, 256>>>(Wq, wq, DMODEL * DMODEL);
    tf32_convert_kernel<<<592, 256>>>(Wk, wk, DMODEL * DMODEL);
    tf32_convert_kernel<<<592, 256>>>(Wv, wv, DMODEL * DMODEL);
    tf32_convert_kernel<<<592, 256>>>(Wo, wo, DMODEL * DMODEL);

    int smem = 4 * GBUF * (int)sizeof(float);   // 73728 B

    dim3 gqkv(DMODEL / 128, MTOT / 128, 3);
    gemm_tc_kernel<<<gqkv, 256, smem>>>(xt, wq, bq, qb, wk, bk, kb, wv, bv, vb, 1);

    attn_tc_kernel<<<dim3(SEQ / 128, NHEAD, BATCH), 256>>>();

    dim3 go(DMODEL / 128, MTOT / 128, 1);
    gemm_tc_kernel<<<go, 256, smem>>>(ab, wo, bo, out, wo, bo, out, wo, bo, out, 0);
}